// round 3
// baseline (speedup 1.0000x reference)
#include <cuda_runtime.h>

// ForwardWarp: forward splatting with Gaussian softmax weights.
// img, counts: (8,1,720,1280) f32; flo: (8,2,720,1280) f32 (ch0 = y shifts W axis, ch1 = x shifts H axis)
// out: [0:S) = img_warp / (one_warp + eps), [S:2S) = one_warp
//
// Splat is RED-instruction-count bound (~1.1 cyc/lane at LSU/LTS). Floor is 2 RED ops
// per pixel: one 16-byte red.global.add.v4.f32 per tap-row covering the two adjacent
// column pairs {img*cw, cw}. Pair addresses are 16B-aligned only for even iy1, so we
// keep TWO accumulators: A (natural layout, even iy1) and B (shifted by one pair, so
// odd iy1 is 16B-aligned). Normalize sums A+B, writes outputs, and re-zeroes the
// scratch (scratch is zero at start from BSS and restored each launch -> no memset).

static constexpr int N_ = 8;
static constexpr int H_ = 720;
static constexpr int W_ = 1280;
static constexpr int S_ = N_ * H_ * W_;   // 7,372,800
static constexpr float EPS_ = 1e-6f;

// A: logical pair j = {img, one} at g_A[2j], g_A[2j+1]           (16B-aligned when j even)
// B: logical pair j at g_B[2j+2], g_B[2j+3]  (slot shifted +1)    (16B-aligned when j odd)
__device__ __align__(16) float g_A[2 * S_];
__device__ __align__(16) float g_B[2 * S_ + 4];

__device__ __forceinline__ void red_v2(float* p, float a, float b) {
    asm volatile("red.global.add.v2.f32 [%0], {%1, %2};"
                 :: "l"(p), "f"(a), "f"(b) : "memory");
}
__device__ __forceinline__ void red_v4(float* p, float a, float b, float c, float d) {
    asm volatile("red.global.add.v4.f32 [%0], {%1, %2, %3, %4};"
                 :: "l"(p), "f"(a), "f"(b), "f"(c), "f"(d) : "memory");
}

__global__ void __launch_bounds__(256) splat_kernel(
    const float* __restrict__ img,
    const float* __restrict__ counts,
    const float* __restrict__ flo)
{
    int idx = blockIdx.x * blockDim.x + threadIdx.x;
    if (idx >= S_) return;

    int w  = idx % W_;
    int hw = idx / W_;
    int h  = hw % H_;
    int n  = hw / H_;

    // flo layout: (N, 2, H, W). channel 0 = y (shifts W axis), channel 1 = x (shifts H axis)
    int flo_base = ((n * 2) * H_ + h) * W_ + w;
    float y = flo[flo_base];
    float x = flo[flo_base + H_ * W_];

    float im = img[idx];
    float c  = counts[idx];

    float x1 = floorf(x);
    float y1 = floorf(y);
    float fx = x - x1;            // (x - x1) in [0,1)
    float fy = y - y1;
    float gx = fx - 1.0f;         // (x - x2)
    float gy = fy - 1.0f;

    float dx1 = fx * fx, dx2 = gx * gx;
    float dy1 = fy * fy, dy2 = gy * gy;

    float w11 = __expf(-(dx1 + dy1));
    float w12 = __expf(-(dx1 + dy2));
    float w21 = __expf(-(dx2 + dy1));
    float w22 = __expf(-(dx2 + dy2));
    float inv = 1.0f / (w11 + w12 + w21 + w22);

    float cinv = c * inv;
    float wa1 = w11 * cinv, wb1 = w12 * cinv;   // row ix1: columns iy1, iy2
    float wa2 = w21 * cinv, wb2 = w22 * cinv;   // row ix2

    int ix1 = (int)x1 + h;
    int ix2 = ix1 + 1;
    int iy1 = (int)y1 + w;
    int iy2 = iy1 + 1;

    bool va = (iy1 >= 0) & (iy1 < W_);
    bool vb = (iy2 >= 0) & (iy2 < W_);
    if (!(va | vb)) return;

    int nb = n * H_;
    bool odd = (iy1 & 1);

    // row 1
    if (ix1 >= 0 && ix1 < H_) {
        int q = (nb + ix1) * W_ + iy1;         // pair index of column iy1
        if (va & vb) {
            if (odd) red_v4(g_B + 2 * q + 2, im * wa1, wa1, im * wb1, wb1);
            else     red_v4(g_A + 2 * q,     im * wa1, wa1, im * wb1, wb1);
        } else if (va) {
            red_v2(g_A + 2 * q,     im * wa1, wa1);
        } else {
            red_v2(g_A + 2 * q + 2, im * wb1, wb1);
        }
    }
    // row 2
    if (ix2 >= 0 && ix2 < H_) {
        int q = (nb + ix2) * W_ + iy1;
        if (va & vb) {
            if (odd) red_v4(g_B + 2 * q + 2, im * wa2, wa2, im * wb2, wb2);
            else     red_v4(g_A + 2 * q,     im * wa2, wa2, im * wb2, wb2);
        } else if (va) {
            red_v2(g_A + 2 * q,     im * wa2, wa2);
        } else {
            red_v2(g_A + 2 * q + 2, im * wb2, wb2);
        }
    }
}

// Each thread handles 4 logical pairs: reads A and B, writes the two output halves,
// and zeroes the scratch it read (restores the all-zero invariant for the next launch).
__global__ void __launch_bounds__(256) normalize_kernel(float* __restrict__ out)
{
    int u = blockIdx.x * blockDim.x + threadIdx.x;
    if (u >= S_ / 4) return;

    // A: pairs 4u..4u+3 -> floats [8u, 8u+8)
    float4 a0 = reinterpret_cast<const float4*>(g_A)[2 * u];
    float4 a1 = reinterpret_cast<const float4*>(g_A)[2 * u + 1];
    // B: pairs 4u..4u+3 -> floats [8u+2, 8u+10), read as 4x float2 (8B-aligned)
    const float2* bptr = reinterpret_cast<const float2*>(g_B + 8 * u + 2);
    float2 b0 = bptr[0];
    float2 b1 = bptr[1];
    float2 b2 = bptr[2];
    float2 b3 = bptr[3];

    float one0 = a0.y + b0.y, one1 = a0.w + b1.y;
    float one2 = a1.y + b2.y, one3 = a1.w + b3.y;

    float4 oimg;
    oimg.x = (a0.x + b0.x) / (one0 + EPS_);
    oimg.y = (a0.z + b1.x) / (one1 + EPS_);
    oimg.z = (a1.x + b2.x) / (one2 + EPS_);
    oimg.w = (a1.z + b3.x) / (one3 + EPS_);
    float4 oone = make_float4(one0, one1, one2, one3);

    reinterpret_cast<float4*>(out)[u] = oimg;
    reinterpret_cast<float4*>(out + S_)[u] = oone;

    // restore zeros
    float4 z4 = make_float4(0.f, 0.f, 0.f, 0.f);
    float2 z2 = make_float2(0.f, 0.f);
    reinterpret_cast<float4*>(g_A)[2 * u] = z4;
    reinterpret_cast<float4*>(g_A)[2 * u + 1] = z4;
    float2* bw = reinterpret_cast<float2*>(g_B + 8 * u + 2);
    bw[0] = z2; bw[1] = z2; bw[2] = z2; bw[3] = z2;
}

extern "C" void kernel_launch(void* const* d_in, const int* in_sizes, int n_in,
                              void* d_out, int out_size)
{
    const float* img    = (const float*)d_in[0];
    const float* counts = (const float*)d_in[1];
    const float* flo    = (const float*)d_in[2];
    float* out = (float*)d_out;

    int threads = 256;
    splat_kernel<<<(S_ + threads - 1) / threads, threads>>>(img, counts, flo);
    normalize_kernel<<<(S_ / 4 + threads - 1) / threads, threads>>>(out);
}

// round 4
// speedup vs baseline: 1.0192x; 1.0192x over previous
#include <cuda_runtime.h>

// ForwardWarp: forward splatting with Gaussian softmax weights.
// img, counts: (8,1,720,1280) f32; flo: (8,2,720,1280) f32 (ch0 = y shifts W axis, ch1 = x shifts H axis)
// out: [0:S) = img_warp / (one_warp + eps), [S:2S) = one_warp
//
// Splat is LTS atomic-QUANTUM bound (~2.9e11 8B-quanta/s): fp32 payload = 32B/pixel = 4
// quanta = ~100us floor. So: single interleaved scratch (min normalize traffic), zeroing
// fused into normalize (scratch starts zero from BSS, each normalize restores it), and a
// 4-stage pipeline over batch chunks: one fused kernel runs splat(chunk i) alongside
// normalize(chunk i-1) -- block-role split, disjoint cells, no sync needed. Normalize
// (bandwidth-bound) hides under splat (atomic-bound).

static constexpr int N_ = 8;
static constexpr int H_ = 720;
static constexpr int W_ = 1280;
static constexpr int S_ = N_ * H_ * W_;        // 7,372,800
static constexpr float EPS_ = 1e-6f;

static constexpr int CHUNKS_ = 4;              // 2 batch images per chunk
static constexpr int P_ = S_ / CHUNKS_;        // 1,843,200 pixels per chunk
static constexpr int THREADS_ = 256;
static constexpr int SPLAT_BLOCKS_ = P_ / THREADS_;        // 7200
static constexpr int NORM_BLOCKS_  = P_ / (4 * THREADS_);  // 1800 (4 cells/thread)

// Interleaved accumulator: pair q = { img_weighted, one_weighted } at g_acc[2q], g_acc[2q+1].
// Zero-initialized (BSS); every normalize restores zeros for its chunk.
__device__ __align__(16) float g_acc[2 * S_];

__device__ __forceinline__ void red_v2(float* p, float a, float b) {
    asm volatile("red.global.add.v2.f32 [%0], {%1, %2};"
                 :: "l"(p), "f"(a), "f"(b) : "memory");
}
__device__ __forceinline__ void red_v4(float* p, float a, float b, float c, float d) {
    asm volatile("red.global.add.v4.f32 [%0], {%1, %2, %3, %4};"
                 :: "l"(p), "f"(a), "f"(b), "f"(c), "f"(d) : "memory");
}

__global__ void __launch_bounds__(256) fused_kernel(
    const float* __restrict__ img,
    const float* __restrict__ counts,
    const float* __restrict__ flo,
    float* __restrict__ out,
    int splat_chunk,      // chunk to splat this launch (>= CHUNKS_ -> none)
    int norm_chunk,       // chunk to normalize this launch (< 0 -> none)
    int norm_blocks)      // number of leading blocks doing normalize
{
    int b = (int)blockIdx.x;

    if (b < norm_blocks) {
        // ---- normalize role: 4 cells per thread ----
        int u = norm_chunk * (P_ / 4) + b * THREADS_ + threadIdx.x;
        float4 a0 = reinterpret_cast<const float4*>(g_acc)[2 * u];       // pairs 4u,4u+1
        float4 a1 = reinterpret_cast<const float4*>(g_acc)[2 * u + 1];   // pairs 4u+2,4u+3

        float4 oimg;
        oimg.x = a0.x / (a0.y + EPS_);
        oimg.y = a0.z / (a0.w + EPS_);
        oimg.z = a1.x / (a1.y + EPS_);
        oimg.w = a1.z / (a1.w + EPS_);
        float4 oone = make_float4(a0.y, a0.w, a1.y, a1.w);

        reinterpret_cast<float4*>(out)[u] = oimg;
        reinterpret_cast<float4*>(out + S_)[u] = oone;

        // restore zeros for next graph replay
        float4 z = make_float4(0.f, 0.f, 0.f, 0.f);
        reinterpret_cast<float4*>(g_acc)[2 * u] = z;
        reinterpret_cast<float4*>(g_acc)[2 * u + 1] = z;
        return;
    }

    // ---- splat role ----
    int idx = splat_chunk * P_ + (b - norm_blocks) * THREADS_ + threadIdx.x;

    int w  = idx % W_;
    int hw = idx / W_;
    int h  = hw % H_;
    int n  = hw / H_;

    // flo layout: (N, 2, H, W). channel 0 = y (shifts W axis), channel 1 = x (shifts H axis)
    int flo_base = ((n * 2) * H_ + h) * W_ + w;
    float y = flo[flo_base];
    float x = flo[flo_base + H_ * W_];

    float im = img[idx];
    float c  = counts[idx];

    float x1 = floorf(x);
    float y1 = floorf(y);
    float fx = x - x1;            // (x - x1) in [0,1)
    float fy = y - y1;
    float gx = fx - 1.0f;         // (x - x2)
    float gy = fy - 1.0f;

    float dx1 = fx * fx, dx2 = gx * gx;
    float dy1 = fy * fy, dy2 = gy * gy;

    float w11 = __expf(-(dx1 + dy1));
    float w12 = __expf(-(dx1 + dy2));
    float w21 = __expf(-(dx2 + dy1));
    float w22 = __expf(-(dx2 + dy2));
    float inv = 1.0f / (w11 + w12 + w21 + w22);

    float cinv = c * inv;
    float wa1 = w11 * cinv, wb1 = w12 * cinv;   // row ix1: columns iy1, iy2
    float wa2 = w21 * cinv, wb2 = w22 * cinv;   // row ix2

    int ix1 = (int)x1 + h;
    int ix2 = ix1 + 1;
    int iy1 = (int)y1 + w;
    int iy2 = iy1 + 1;

    bool va = (iy1 >= 0) & (iy1 < W_);
    bool vb = (iy2 >= 0) & (iy2 < W_);
    if (!(va | vb)) return;

    int nb = n * H_;
    bool aligned = ((iy1 & 1) == 0);

    // row 1
    if (ix1 >= 0 && ix1 < H_) {
        int q = (nb + ix1) * W_ + iy1;
        float* base = g_acc + 2 * q;
        if (va & vb) {
            if (aligned) red_v4(base, im * wa1, wa1, im * wb1, wb1);
            else { red_v2(base, im * wa1, wa1); red_v2(base + 2, im * wb1, wb1); }
        } else if (va) {
            red_v2(base, im * wa1, wa1);
        } else {
            red_v2(base + 2, im * wb1, wb1);
        }
    }
    // row 2
    if (ix2 >= 0 && ix2 < H_) {
        int q = (nb + ix2) * W_ + iy1;
        float* base = g_acc + 2 * q;
        if (va & vb) {
            if (aligned) red_v4(base, im * wa2, wa2, im * wb2, wb2);
            else { red_v2(base, im * wa2, wa2); red_v2(base + 2, im * wb2, wb2); }
        } else if (va) {
            red_v2(base, im * wa2, wa2);
        } else {
            red_v2(base + 2, im * wb2, wb2);
        }
    }
}

extern "C" void kernel_launch(void* const* d_in, const int* in_sizes, int n_in,
                              void* d_out, int out_size)
{
    const float* img    = (const float*)d_in[0];
    const float* counts = (const float*)d_in[1];
    const float* flo    = (const float*)d_in[2];
    float* out = (float*)d_out;

    // Pipeline: launch i does splat(chunk i) concurrently with normalize(chunk i-1).
    for (int i = 0; i <= CHUNKS_; i++) {
        int sc = i;
        int nc = i - 1;
        int nb = (nc >= 0) ? NORM_BLOCKS_ : 0;
        int sb = (sc < CHUNKS_) ? SPLAT_BLOCKS_ : 0;
        fused_kernel<<<nb + sb, THREADS_>>>(img, counts, flo, out, sc, nc, nb);
    }
}